// round 4
// baseline (speedup 1.0000x reference)
#include <cuda_runtime.h>
#include <math.h>

#define H 1024
#define L 4096
#define V 29
#define NB 148           // 1 block/SM, co-resident (GB300 has >=148 SMs)
#define NT 1024
#define WPB 32
#define WTOT (NB * WPB)  // 4736 warps

// ---------------- scratch (device globals) ----------------------------------
__device__ float g_scp[2 * L];         // score partials: [2*row+half]
__device__ float g_hh[4 * H];          // W_hh @ h0 full rows
__device__ float g_attn_applied[H];
__device__ float g_xp[4 * H];          // combine partials: [4*row+q]
__device__ float g_gp[8 * H];          // W_ih@x partials: [2*row+half]
__device__ unsigned g_cnt = 0;
__device__ volatile unsigned g_flag = 0;

// ---------------- helpers ----------------------------------------------------
__device__ __forceinline__ float warp_sum(float v) {
#pragma unroll
    for (int o = 16; o; o >>= 1) v += __shfl_xor_sync(0xffffffffu, v, o);
    return v;
}
__device__ __forceinline__ float warp_max(float v) {
#pragma unroll
    for (int o = 16; o; o >>= 1) v = fmaxf(v, __shfl_xor_sync(0xffffffffu, v, o));
    return v;
}
__device__ __forceinline__ float sigmoidf_(float x) { return 1.0f / (1.0f + expf(-x)); }
__device__ __forceinline__ float dot4(float4 a, float4 b) {
    return a.x * b.x + a.y * b.y + a.z * b.z + a.w * b.w;
}
// 1024-elt dot: 8 float4 per lane, dual accumulators, fully unrolled
__device__ __forceinline__ float dot_chunk8(const float4* __restrict__ w,
                                            const float4* __restrict__ v, int lane) {
    float a0 = 0.f, a1 = 0.f;
#pragma unroll
    for (int k = 0; k < 8; k += 2) {
        a0 += dot4(w[lane + 32 * k],       v[lane + 32 * k]);
        a1 += dot4(w[lane + 32 * (k + 1)], v[lane + 32 * (k + 1)]);
    }
    return a0 + a1;
}
// 512-elt dot: 4 float4 per lane
__device__ __forceinline__ float dot_chunk4(const float4* __restrict__ w,
                                            const float4* __restrict__ v, int lane) {
    float a0 = 0.f, a1 = 0.f;
#pragma unroll
    for (int k = 0; k < 4; k += 2) {
        a0 += dot4(w[lane + 32 * k],       v[lane + 32 * k]);
        a1 += dot4(w[lane + 32 * (k + 1)], v[lane + 32 * (k + 1)]);
    }
    return a0 + a1;
}

// sense-reversing grid barrier; even # of uses -> flag returns to 0 for replay
__device__ __forceinline__ void grid_barrier(unsigned sense) {
    __syncthreads();
    if (threadIdx.x == 0) {
        __threadfence();
        unsigned old = atomicAdd(&g_cnt, 1u);
        if (old == NB - 1) {
            g_cnt = 0;
            __threadfence();
            g_flag = sense;
        } else {
            while (g_flag != sense) { __nanosleep(32); }
        }
        __threadfence();
    }
    __syncthreads();
}

// ---------------- the whole decoder step in one kernel -----------------------
__global__ void __launch_bounds__(NT, 1)
k_decoder(const int* __restrict__ tok,
          const float* __restrict__ h0,
          const float* __restrict__ c0,
          const float* __restrict__ enc,
          const float* __restrict__ emb,
          const float* __restrict__ attn_W,
          const float* __restrict__ attn_b,
          const float* __restrict__ comb_W,
          const float* __restrict__ comb_b,
          const float* __restrict__ W_ih,
          const float* __restrict__ W_hh,
          const float* __restrict__ b_ih,
          const float* __restrict__ b_hh,
          const float* __restrict__ out_W,
          const float* __restrict__ out_b,
          float* __restrict__ out) {
    __shared__ float s[2 * H];
    __shared__ float red[32];
    __shared__ float bcast;
    __shared__ float wts[28];
    __shared__ float z[32];

    const int t = threadIdx.x;
    const int warp = t >> 5, lane = t & 31;
    const int wg = blockIdx.x * WPB + warp;     // 0..4735
    float* attn_out = out + V + 2 * H;          // [lp | h | c | attn_w]

    // ===== Phase A: scores (8192 half-row chunks) + W_hh@h0 (4096 chunks) ===
    {
        const float* erow = emb + (size_t)tok[0] * H;
        s[t] = erow[t];
        s[H + t] = h0[t];
        if (blockIdx.x == 0) g_attn_applied[t] = 0.0f;
        __syncthreads();

        const float4* sv = (const float4*)s;       // [emb | h0], 512 float4
#pragma unroll
        for (int c = wg; c < 3 * L; c += WTOT) {    // 12288 chunks
            if (c < 2 * L) {                        // score chunk
                int row = c >> 1, half = c & 1;
                const float4* w = (const float4*)(attn_W + (size_t)row * (2 * H) + half * H);
                float acc = dot_chunk8(w, sv + half * (H / 4), lane);
                acc = warp_sum(acc);
                if (lane == 0) g_scp[c] = acc;
            } else {                                // hh chunk (full row)
                int row = c - 2 * L;
                const float4* w = (const float4*)(W_hh + (size_t)row * H);
                float acc = dot_chunk8(w, sv + (H / 4), lane);
                acc = warp_sum(acc);
                if (lane == 0) g_hh[row] = acc;
            }
        }
    }
    grid_barrier(1);

    // ===== Phase B: softmax (redundant per-block reduce) + weighted enc sum =
    {
        const float2* sp = (const float2*)g_scp;    // pair = (half0, half1)
        float sc[4];
        float m = -1e30f;
#pragma unroll
        for (int k = 0; k < 4; k++) {
            float2 p = sp[t + k * 1024];
            sc[k] = p.x + p.y + attn_b[t + k * 1024];
            m = fmaxf(m, sc[k]);
        }
        m = warp_max(m);
        if (lane == 0) red[warp] = m;
        __syncthreads();
        if (warp == 0) {
            float x = red[lane];
            x = warp_max(x);
            if (lane == 0) bcast = x;
        }
        __syncthreads();
        const float M = bcast;

        float sum = 0.0f;
#pragma unroll
        for (int k = 0; k < 4; k++) sum += expf(sc[k] - M);
        sum = warp_sum(sum);
        __syncthreads();
        if (lane == 0) red[warp] = sum;
        __syncthreads();
        if (warp == 0) {
            float x = red[lane];
            x = warp_sum(x);
            if (lane == 0) bcast = x;
        }
        __syncthreads();
        const float invS = 1.0f / bcast;

        const int lb = blockIdx.x * 28;             // 28 enc rows per block
        if (t < 28 && lb + t < L) {
            float2 p = sp[lb + t];
            float w = expf(p.x + p.y + attn_b[lb + t] - M) * invS;
            wts[t] = w;
            attn_out[lb + t] = w;
        }
        __syncthreads();

        if (lb < L) {
            float acc = 0.0f;
            const float* e = enc + (size_t)lb * H + t;
            int nr = min(28, L - lb);
#pragma unroll 7
            for (int r = 0; r < nr; r++) acc += wts[r] * e[(size_t)r * H];
            atomicAdd(&g_attn_applied[t], acc);
        }
    }
    grid_barrier(0);

    // ===== Phase C: x partials = comb_W @ [emb; attn] (4096 quarter chunks) =
    {
        s[H + t] = g_attn_applied[t];   // emb still in s[0..H)
        __syncthreads();
        const float4* sv = (const float4*)s;
        if (wg < 4 * H) {               // 4096 chunks of 512 elts
            int row = wg >> 2, q = wg & 3;
            const float4* w = (const float4*)(comb_W + (size_t)row * (2 * H) + q * 512);
            float acc = dot_chunk4(w, sv + q * 128, lane);
            acc = warp_sum(acc);
            if (lane == 0) g_xp[wg] = acc;
        }
    }
    grid_barrier(1);

    // ===== Phase D: gate partials = W_ih @ x (8192 half-row chunks) =========
    {
        // combine x partials + bias + relu while loading into shared
        const float4* xp = (const float4*)g_xp;
        float4 p = xp[t];
        s[t] = fmaxf(p.x + p.y + p.z + p.w + comb_b[t], 0.0f);
        __syncthreads();

        const float4* sv = (const float4*)s;        // x, 256 float4
#pragma unroll
        for (int c = wg; c < 8 * H; c += WTOT) {    // 8192 chunks of 512
            int row = c >> 1, half = c & 1;
            const float4* w = (const float4*)(W_ih + (size_t)row * H + half * 512);
            float acc = dot_chunk4(w, sv + half * 128, lane);
            acc = warp_sum(acc);
            if (lane == 0) g_gp[c] = acc;
        }
    }
    grid_barrier(0);

    // ===== Phase E: LSTM pointwise + out proj + log_softmax (block 0) =======
    if (blockIdx.x == 0) {
        const float2* gp = (const float2*)g_gp;     // pair per row
        float2 pi = gp[t];
        float2 pf = gp[H + t];
        float2 pg = gp[2 * H + t];
        float2 po = gp[3 * H + t];
        float ig = pi.x + pi.y + g_hh[t]         + b_ih[t]         + b_hh[t];
        float fg = pf.x + pf.y + g_hh[H + t]     + b_ih[H + t]     + b_hh[H + t];
        float gg = pg.x + pg.y + g_hh[2 * H + t] + b_ih[2 * H + t] + b_hh[2 * H + t];
        float og = po.x + po.y + g_hh[3 * H + t] + b_ih[3 * H + t] + b_hh[3 * H + t];
        float c = sigmoidf_(fg) * c0[t] + sigmoidf_(ig) * tanhf(gg);
        float h = sigmoidf_(og) * tanhf(c);
        out[V + t] = h;
        out[V + H + t] = c;
        s[t] = h;
        __syncthreads();

        if (warp < V) {
            const float4* wr = (const float4*)(out_W + (size_t)warp * H);
            const float4* hv = (const float4*)s;
            float acc = 0.0f;
#pragma unroll
            for (int k = lane; k < H / 4; k += 32) acc += dot4(wr[k], hv[k]);
            acc = warp_sum(acc);
            if (lane == 0) z[warp] = acc + out_b[warp];
        }
        __syncthreads();

        if (t == 0) {
            float m = -1e30f;
            for (int r = 0; r < V; r++) m = fmaxf(m, z[r]);
            float ssum = 0.0f;
            for (int r = 0; r < V; r++) ssum += expf(z[r] - m);
            float ls = m + logf(ssum);
            for (int r = 0; r < V; r++) out[r] = z[r] - ls;
        }
    }
}

// ---------------- launch ------------------------------------------------------
extern "C" void kernel_launch(void* const* d_in, const int* in_sizes, int n_in,
                              void* d_out, int out_size) {
    const int*   tok    = (const int*)  d_in[0];
    const float* h0     = (const float*)d_in[1];
    const float* c0     = (const float*)d_in[2];
    const float* enc    = (const float*)d_in[3];
    const float* emb    = (const float*)d_in[4];
    const float* attn_W = (const float*)d_in[5];
    const float* attn_b = (const float*)d_in[6];
    const float* comb_W = (const float*)d_in[7];
    const float* comb_b = (const float*)d_in[8];
    const float* W_ih   = (const float*)d_in[9];
    const float* W_hh   = (const float*)d_in[10];
    const float* b_ih   = (const float*)d_in[11];
    const float* b_hh   = (const float*)d_in[12];
    const float* out_W  = (const float*)d_in[13];
    const float* out_b  = (const float*)d_in[14];
    float* out = (float*)d_out;

    k_decoder<<<NB, NT>>>(tok, h0, c0, enc, emb, attn_W, attn_b,
                          comb_W, comb_b, W_ih, W_hh, b_ih, b_hh,
                          out_W, out_b, out);
}